// round 2
// baseline (speedup 1.0000x reference)
#include <cuda_runtime.h>
#include <cuda_fp16.h>
#include <cstdint>

// ===========================================================================
// TernaryLinear: out[8192,11008] = x[8192,4096] @ sign(W)[11008,4096]^T + bias
//
// sm_100 (no 'a' features!) path: fp16 x, fp16 sign(W), mma.sync.m16n8k16
// with fp32 accumulators, cp.async 6-stage SMEM pipeline, ldmatrix frags.
// CTA tile 128x256, 8 warps, warp tile 64x64.
// ===========================================================================

#define DEVFN __device__ __forceinline__

static constexpr int Mdim = 8192, Ndim = 11008, Kdim = 4096;
static constexpr int BM = 128, BN = 256;
static constexpr int STRIDE = 80;                 // 64B K-chunk + 16B pad (conflict-free)
static constexpr int NSTAGES = 6;
static constexpr int A_BYTES = BM * STRIDE;       // 10240
static constexpr int B_BYTES = BN * STRIDE;       // 20480
static constexpr int STAGE = A_BYTES + B_BYTES;   // 30720
static constexpr int SMEM_TOTAL = NSTAGES * STAGE;// 184320
static constexpr int KITERS = (Kdim * 2) / 64;    // 128 K-chunks of 32 fp16

// -------------------- scratch (device globals; no cudaMalloc) --------------
__device__ __align__(128) unsigned char g_xh[(size_t)Mdim * Kdim * 2];   // fp16 x
__device__ __align__(128) unsigned char g_wh[(size_t)Ndim * Kdim * 2];   // fp16 sign(W)

// -------------------- PTX helpers ------------------------------------------
DEVFN uint32_t smem_u32(const void* p) {
    uint32_t a;
    asm("{ .reg .u64 t; cvta.to.shared.u64 t, %1; cvt.u32.u64 %0, t; }"
        : "=r"(a) : "l"(p));
    return a;
}

DEVFN void cp16(uint32_t dst, const void* src) {
    asm volatile("cp.async.cg.shared.global [%0], [%1], 16;"
                 :: "r"(dst), "l"(src) : "memory");
}
DEVFN void cp_commit() { asm volatile("cp.async.commit_group;" ::: "memory"); }
template <int N> DEVFN void cp_wait() {
    asm volatile("cp.async.wait_group %0;" :: "n"(N) : "memory");
}

DEVFN void ldsm4(uint32_t* r, uint32_t addr) {
    asm volatile("ldmatrix.sync.aligned.m8n8.x4.shared.b16 {%0,%1,%2,%3}, [%4];"
                 : "=r"(r[0]), "=r"(r[1]), "=r"(r[2]), "=r"(r[3]) : "r"(addr));
}

DEVFN void mma16816(float* d, const uint32_t* a, uint32_t b0, uint32_t b1) {
    asm volatile(
        "mma.sync.aligned.m16n8k16.row.col.f32.f16.f16.f32 "
        "{%0,%1,%2,%3}, {%4,%5,%6,%7}, {%8,%9}, {%0,%1,%2,%3};"
        : "+f"(d[0]), "+f"(d[1]), "+f"(d[2]), "+f"(d[3])
        : "r"(a[0]), "r"(a[1]), "r"(a[2]), "r"(a[3]), "r"(b0), "r"(b1));
}

// -------------------- preprocessing ----------------------------------------
__global__ void prep_x(const float4* __restrict__ x, uint2* __restrict__ o) {
    int i = blockIdx.x * blockDim.x + threadIdx.x;
    float4 v = x[i];
    __half2 h0 = __floats2half2_rn(v.x, v.y);
    __half2 h1 = __floats2half2_rn(v.z, v.w);
    uint2 u;
    u.x = *reinterpret_cast<uint32_t*>(&h0);
    u.y = *reinterpret_cast<uint32_t*>(&h1);
    o[i] = u;
}

__global__ void prep_w(const float4* __restrict__ w, uint2* __restrict__ o) {
    int i = blockIdx.x * blockDim.x + threadIdx.x;
    float4 v = w[i];
    float f[4] = {v.x, v.y, v.z, v.w};
    uint32_t s[4];
#pragma unroll
    for (int j = 0; j < 4; ++j)
        s[j] = f[j] > 0.f ? 0x3C00u : (f[j] < 0.f ? 0xBC00u : 0u);
    uint2 u;
    u.x = s[0] | (s[1] << 16);
    u.y = s[2] | (s[3] << 16);
    o[i] = u;
}

// -------------------- GEMM kernel ------------------------------------------
__global__ void __launch_bounds__(256, 1) gemm_f16(
    const unsigned char* __restrict__ A,   // fp16 [M][K]
    const unsigned char* __restrict__ B,   // fp16 [N][K]
    const float* __restrict__ bias,
    float* __restrict__ out)
{
    extern __shared__ __align__(128) unsigned char smem[];
    const uint32_t sbase = smem_u32(smem);
    const int tid = threadIdx.x;
    const int lane = tid & 31;
    const int wid = tid >> 5;
    const int wm = wid >> 2;        // 0..1
    const int wn = wid & 3;         // 0..3
    const int m0 = blockIdx.y * BM;
    const int n0 = blockIdx.x * BN;

    // ---- cp.async source/dest bases (each thread owns chunk col tid&3) ----
    const int ar = tid >> 2;             // 0..63
    const int ac = (tid & 3) * 16;       // byte within 64B row chunk
    const size_t rowbytes = (size_t)Kdim * 2;   // 8192
    const unsigned char* gA = A + (size_t)(m0 + ar) * rowbytes + ac;
    const unsigned char* gB = B + (size_t)(n0 + ar) * rowbytes + ac;
    const uint32_t sA = sbase + ar * STRIDE + ac;
    const uint32_t sB = sbase + A_BYTES + ar * STRIDE + ac;

    // ---- ldmatrix per-lane addresses ----
    uint32_t aAddr[4], bAddr[4];
    {
        int arow = wm * 64 + (lane & 15);
        int acol = (lane & 16);              // 0 or 16 bytes
        int brow = wn * 64 + ((lane >> 4) << 3) + (lane & 7);
        int bcol = (lane & 8) << 1;          // 0 or 16 bytes
#pragma unroll
        for (int f = 0; f < 4; ++f) {
            aAddr[f] = sbase + (arow + f * 16) * STRIDE + acol;
            bAddr[f] = sbase + A_BYTES + (brow + f * 16) * STRIDE + bcol;
        }
    }

    float acc[4][8][4];
#pragma unroll
    for (int i = 0; i < 4; ++i)
#pragma unroll
        for (int j = 0; j < 8; ++j)
#pragma unroll
            for (int k = 0; k < 4; ++k) acc[i][j][k] = 0.f;

    // ---- stage loader ----
    auto load_stage = [&](int it, int s) {
        const uint32_t so = (uint32_t)s * STAGE;
        const size_t ko = (size_t)it * 64;
        cp16(sA + so, gA + ko);
        cp16(sA + so + 64 * STRIDE, gA + ko + 64 * rowbytes);
#pragma unroll
        for (int j = 0; j < 4; ++j)
            cp16(sB + so + j * 64 * STRIDE, gB + ko + (size_t)j * 64 * rowbytes);
    };

    // ---- prologue: fill NSTAGES-1 stages ----
#pragma unroll
    for (int s = 0; s < NSTAGES - 1; ++s) {
        load_stage(s, s);
        cp_commit();
    }

    int stage = 0, nxt_stage = NSTAGES - 1;
    for (int i = 0; i < KITERS; ++i) {
        cp_wait<NSTAGES - 2>();
        __syncthreads();

        // issue next load (overwrites stage computed last iteration; the
        // __syncthreads above guarantees everyone is done with it)
        int nxt = i + NSTAGES - 1;
        if (nxt < KITERS) load_stage(nxt, nxt_stage);
        cp_commit();   // empty commits at tail keep group numbering uniform

        // compute this stage: 2 k-steps of 16
        const uint32_t off = (uint32_t)stage * STAGE;
#pragma unroll
        for (int ks = 0; ks < 2; ++ks) {
            const uint32_t ko = off + ks * 32;
            uint32_t a[4][4], b[4][4];
#pragma unroll
            for (int f = 0; f < 4; ++f) ldsm4(a[f], aAddr[f] + ko);
#pragma unroll
            for (int p = 0; p < 4; ++p) ldsm4(b[p], bAddr[p] + ko);
#pragma unroll
            for (int f = 0; f < 4; ++f)
#pragma unroll
                for (int p = 0; p < 4; ++p) {
                    mma16816(acc[f][2 * p], a[f], b[p][0], b[p][1]);
                    mma16816(acc[f][2 * p + 1], a[f], b[p][2], b[p][3]);
                }
        }

        if (++stage == NSTAGES) stage = 0;
        if (++nxt_stage == NSTAGES) nxt_stage = 0;
    }

    // ---- epilogue: +bias, write float2 ----
    const int r0 = m0 + wm * 64 + (lane >> 2);
    const int c0 = n0 + wn * 64 + (lane & 3) * 2;
#pragma unroll
    for (int f = 0; f < 4; ++f) {
#pragma unroll
        for (int g = 0; g < 8; ++g) {
            int row = r0 + f * 16;
            int col = c0 + g * 8;
            float2 bz = *reinterpret_cast<const float2*>(bias + col);
            float2 o01, o23;
            o01.x = acc[f][g][0] + bz.x;
            o01.y = acc[f][g][1] + bz.y;
            o23.x = acc[f][g][2] + bz.x;
            o23.y = acc[f][g][3] + bz.y;
            *reinterpret_cast<float2*>(out + (size_t)row * Ndim + col) = o01;
            *reinterpret_cast<float2*>(out + (size_t)(row + 8) * Ndim + col) = o23;
        }
    }
}

// -------------------- host side --------------------------------------------
extern "C" void kernel_launch(void* const* d_in, const int* in_sizes, int n_in,
                              void* d_out, int out_size) {
    const float* x = (const float*)d_in[0];
    const float* w = (const float*)d_in[1];
    const float* bias = (const float*)d_in[2];
    float* out = (float*)d_out;

    void *p_xh = nullptr, *p_wh = nullptr;
    cudaGetSymbolAddress(&p_xh, g_xh);
    cudaGetSymbolAddress(&p_wh, g_wh);

    prep_x<<<(Mdim * Kdim / 4) / 256, 256>>>((const float4*)x, (uint2*)p_xh);
    prep_w<<<(Ndim * Kdim / 4) / 256, 256>>>((const float4*)w, (uint2*)p_wh);

    static bool attr_set = false;
    if (!attr_set) {
        cudaFuncSetAttribute(gemm_f16,
                             cudaFuncAttributeMaxDynamicSharedMemorySize,
                             SMEM_TOTAL);
        attr_set = true;
    }

    dim3 grid(Ndim / BN, Mdim / BM);   // (43, 64)
    gemm_f16<<<grid, 256, SMEM_TOTAL>>>(
        (const unsigned char*)p_xh, (const unsigned char*)p_wh, bias, out);
}

// round 4
// speedup vs baseline: 1.5021x; 1.5021x over previous
#include <cuda_runtime.h>
#include <cuda_fp16.h>
#include <cstdint>

// ===========================================================================
// TernaryLinear: out[8192,11008] = x[8192,4096] @ sign(W)[11008,4096]^T + bias
//
// sm_100 (no 'a' features) path: fp16 x, fp16 sign(W), mma.sync.m16n8k16
// f32 accumulators, cp.async 6-stage pipeline, ldmatrix frags with explicit
// double-buffering, L2-friendly raster. CTA 128x256, 8 warps, warp 64x64.
// R4: fixed stage-residency race (wait<2> instead of wait<3> in mainloop).
// ===========================================================================

#define DEVFN __device__ __forceinline__

static constexpr int Mdim = 8192, Ndim = 11008, Kdim = 4096;
static constexpr int BM = 128, BN = 256;
static constexpr int STRIDE = 80;                 // 64B K-chunk + 16B pad
static constexpr int NSTAGES = 6;
static constexpr int A_BYTES = BM * STRIDE;       // 10240
static constexpr int B_BYTES = BN * STRIDE;       // 20480
static constexpr int STAGE = A_BYTES + B_BYTES;   // 30720
static constexpr int SMEM_TOTAL = NSTAGES * STAGE;// 184320
static constexpr int KITERS = (Kdim * 2) / 64;    // 128 BK=32 chunks

static constexpr int MTILES = Mdim / BM;          // 64
static constexpr int NTILES = Ndim / BN;          // 43
static constexpr int GROUP_M = 16;                // raster: 16 M-tiles per band

// -------------------- scratch (device globals; no cudaMalloc) --------------
__device__ __align__(128) unsigned char g_xh[(size_t)Mdim * Kdim * 2];
__device__ __align__(128) unsigned char g_wh[(size_t)Ndim * Kdim * 2];

// -------------------- PTX helpers ------------------------------------------
DEVFN uint32_t smem_u32(const void* p) {
    uint32_t a;
    asm("{ .reg .u64 t; cvta.to.shared.u64 t, %1; cvt.u32.u64 %0, t; }"
        : "=r"(a) : "l"(p));
    return a;
}
DEVFN void cp16(uint32_t dst, const void* src) {
    asm volatile("cp.async.cg.shared.global [%0], [%1], 16;"
                 :: "r"(dst), "l"(src) : "memory");
}
DEVFN void cp_commit() { asm volatile("cp.async.commit_group;" ::: "memory"); }
template <int N> DEVFN void cp_wait() {
    asm volatile("cp.async.wait_group %0;" :: "n"(N) : "memory");
}
DEVFN void ldsm4(uint32_t* r, uint32_t addr) {
    asm volatile("ldmatrix.sync.aligned.m8n8.x4.shared.b16 {%0,%1,%2,%3}, [%4];"
                 : "=r"(r[0]), "=r"(r[1]), "=r"(r[2]), "=r"(r[3]) : "r"(addr));
}
DEVFN void mma16816(float* d, const uint32_t* a, uint32_t b0, uint32_t b1) {
    asm volatile(
        "mma.sync.aligned.m16n8k16.row.col.f32.f16.f16.f32 "
        "{%0,%1,%2,%3}, {%4,%5,%6,%7}, {%8,%9}, {%0,%1,%2,%3};"
        : "+f"(d[0]), "+f"(d[1]), "+f"(d[2]), "+f"(d[3])
        : "r"(a[0]), "r"(a[1]), "r"(a[2]), "r"(a[3]), "r"(b0), "r"(b1));
}

// -------------------- fused preprocessing ----------------------------------
static constexpr int XBLK = (Mdim * Kdim / 4) / 256;   // 32768
static constexpr int WBLK = (Ndim * Kdim / 4) / 256;   // 44032

__global__ void prep_fused(const float4* __restrict__ x,
                           const float4* __restrict__ w,
                           uint2* __restrict__ xh, uint2* __restrict__ wh) {
    int b = blockIdx.x;
    if (b < XBLK) {
        int i = b * 256 + threadIdx.x;
        float4 v = x[i];
        __half2 h0 = __floats2half2_rn(v.x, v.y);
        __half2 h1 = __floats2half2_rn(v.z, v.w);
        uint2 u;
        u.x = *reinterpret_cast<uint32_t*>(&h0);
        u.y = *reinterpret_cast<uint32_t*>(&h1);
        xh[i] = u;
    } else {
        int i = (b - XBLK) * 256 + threadIdx.x;
        float4 v = w[i];
        float f[4] = {v.x, v.y, v.z, v.w};
        uint32_t s[4];
#pragma unroll
        for (int j = 0; j < 4; ++j)
            s[j] = f[j] > 0.f ? 0x3C00u : (f[j] < 0.f ? 0xBC00u : 0u);
        uint2 u;
        u.x = s[0] | (s[1] << 16);
        u.y = s[2] | (s[3] << 16);
        wh[i] = u;
    }
}

// -------------------- GEMM kernel ------------------------------------------
__global__ void __launch_bounds__(256, 1) gemm_f16(
    const unsigned char* __restrict__ A,   // fp16 [M][K]
    const unsigned char* __restrict__ B,   // fp16 [N][K]
    const float* __restrict__ bias,
    float* __restrict__ out)
{
    extern __shared__ __align__(128) unsigned char smem[];
    const uint32_t sbase = smem_u32(smem);
    const int tid = threadIdx.x;
    const int lane = tid & 31;
    const int wid = tid >> 5;
    const int wm = wid >> 2;        // 0..1
    const int wn = wid & 3;         // 0..3

    // ---- L2-friendly raster: bands of GROUP_M M-tiles sweeping N ----
    const int bid = blockIdx.y * gridDim.x + blockIdx.x;
    const int band = bid / (GROUP_M * NTILES);
    const int rem = bid % (GROUP_M * NTILES);
    const int bm = band * GROUP_M + (rem % GROUP_M);
    const int bn = rem / GROUP_M;
    const int m0 = bm * BM;
    const int n0 = bn * BN;

    // ---- cp.async addressing ----
    const int ar = tid >> 2;
    const int ac = (tid & 3) * 16;
    const size_t rowbytes = (size_t)Kdim * 2;
    const unsigned char* gA = A + (size_t)(m0 + ar) * rowbytes + ac;
    const unsigned char* gB = B + (size_t)(n0 + ar) * rowbytes + ac;
    const uint32_t sA = sbase + ar * STRIDE + ac;
    const uint32_t sB = sbase + A_BYTES + ar * STRIDE + ac;

    // ---- ldmatrix per-lane addresses ----
    uint32_t aAddr[4], bAddr[4];
    {
        int arow = wm * 64 + (lane & 15);
        int acol = (lane & 16);
        int brow = wn * 64 + ((lane >> 4) << 3) + (lane & 7);
        int bcol = (lane & 8) << 1;
#pragma unroll
        for (int f = 0; f < 4; ++f) {
            aAddr[f] = sbase + (arow + f * 16) * STRIDE + acol;
            bAddr[f] = sbase + A_BYTES + (brow + f * 16) * STRIDE + bcol;
        }
    }

    float acc[4][8][4];
#pragma unroll
    for (int i = 0; i < 4; ++i)
#pragma unroll
        for (int j = 0; j < 8; ++j)
#pragma unroll
            for (int k = 0; k < 4; ++k) acc[i][j][k] = 0.f;

    auto load_stage = [&](int it, int s) {
        const uint32_t so = (uint32_t)s * STAGE;
        const size_t ko = (size_t)it * 64;
        cp16(sA + so, gA + ko);
        cp16(sA + so + 64 * STRIDE, gA + ko + 64 * rowbytes);
#pragma unroll
        for (int j = 0; j < 4; ++j)
            cp16(sB + so + j * 64 * STRIDE, gB + ko + (size_t)j * 64 * rowbytes);
    };

    // ---- prologue: issue 5 stages, wait until stages 0,1 resident ----
#pragma unroll
    for (int s = 0; s < NSTAGES - 1; ++s) {
        load_stage(s, s);
        cp_commit();
    }
    cp_wait<NSTAGES - 3>();       // <=3 pending -> stages 0,1 resident
    __syncthreads();

    // frag double buffers
    uint32_t afr[2][4][4], bfr[2][4][4];
#pragma unroll
    for (int f = 0; f < 4; ++f) ldsm4(afr[0][f], aAddr[f]);
#pragma unroll
    for (int p = 0; p < 4; ++p) ldsm4(bfr[0][p], bAddr[p]);

    int cur = 0;
    for (int i = 0; i < KITERS; ++i) {
        const uint32_t soff = (uint32_t)(i % NSTAGES) * STAGE;
        const uint32_t noff = (uint32_t)((i + 1) % NSTAGES) * STAGE;

        // ks0: prefetch ks1 frags, mma on ks0 frags
#pragma unroll
        for (int f = 0; f < 4; ++f) ldsm4(afr[cur ^ 1][f], aAddr[f] + soff + 32);
#pragma unroll
        for (int p = 0; p < 4; ++p) ldsm4(bfr[cur ^ 1][p], bAddr[p] + soff + 32);
#pragma unroll
        for (int f = 0; f < 4; ++f)
#pragma unroll
            for (int p = 0; p < 4; ++p) {
                mma16816(acc[f][2 * p], afr[cur][f], bfr[cur][p][0], bfr[cur][p][1]);
                mma16816(acc[f][2 * p + 1], afr[cur][f], bfr[cur][p][2], bfr[cur][p][3]);
            }
        cur ^= 1;

        // ks1: prefetch next-stage ks0 frags, mma on ks1 frags
#pragma unroll
        for (int f = 0; f < 4; ++f) ldsm4(afr[cur ^ 1][f], aAddr[f] + noff);
#pragma unroll
        for (int p = 0; p < 4; ++p) ldsm4(bfr[cur ^ 1][p], bAddr[p] + noff);
#pragma unroll
        for (int f = 0; f < 4; ++f)
#pragma unroll
            for (int p = 0; p < 4; ++p) {
                mma16816(acc[f][2 * p], afr[cur][f], bfr[cur][p][0], bfr[cur][p][1]);
                mma16816(acc[f][2 * p + 1], afr[cur][f], bfr[cur][p][2], bfr[cur][p][3]);
            }
        cur ^= 1;

        // pipeline control. wait<2>: after 5+i commits, forces i+3 groups
        // complete -> stages 0..i+2 resident -> iter i+1's noff (stage i+2)
        // frag prefetch is safe. (wait<3> here was an off-by-one race.)
        cp_wait<NSTAGES - 4>();
        __syncthreads();
        if (i + NSTAGES - 1 < KITERS) load_stage(i + NSTAGES - 1, (i + NSTAGES - 1) % NSTAGES);
        cp_commit();
    }

    // ---- epilogue: +bias, write float2 ----
    const int r0 = m0 + wm * 64 + (lane >> 2);
    const int c0 = n0 + wn * 64 + (lane & 3) * 2;
#pragma unroll
    for (int f = 0; f < 4; ++f) {
#pragma unroll
        for (int g = 0; g < 8; ++g) {
            int row = r0 + f * 16;
            int col = c0 + g * 8;
            float2 bz = *reinterpret_cast<const float2*>(bias + col);
            float2 o01, o23;
            o01.x = acc[f][g][0] + bz.x;
            o01.y = acc[f][g][1] + bz.y;
            o23.x = acc[f][g][2] + bz.x;
            o23.y = acc[f][g][3] + bz.y;
            *reinterpret_cast<float2*>(out + (size_t)row * Ndim + col) = o01;
            *reinterpret_cast<float2*>(out + (size_t)(row + 8) * Ndim + col) = o23;
        }
    }
}

// -------------------- host side --------------------------------------------
extern "C" void kernel_launch(void* const* d_in, const int* in_sizes, int n_in,
                              void* d_out, int out_size) {
    const float* x = (const float*)d_in[0];
    const float* w = (const float*)d_in[1];
    const float* bias = (const float*)d_in[2];
    float* out = (float*)d_out;

    void *p_xh = nullptr, *p_wh = nullptr;
    cudaGetSymbolAddress(&p_xh, g_xh);
    cudaGetSymbolAddress(&p_wh, g_wh);

    prep_fused<<<XBLK + WBLK, 256>>>((const float4*)x, (const float4*)w,
                                     (uint2*)p_xh, (uint2*)p_wh);

    static bool attr_set = false;
    if (!attr_set) {
        cudaFuncSetAttribute(gemm_f16,
                             cudaFuncAttributeMaxDynamicSharedMemorySize,
                             SMEM_TOTAL);
        attr_set = true;
    }

    dim3 grid(NTILES, MTILES);   // 2752 CTAs, rasterized in-kernel
    gemm_f16<<<grid, 256, SMEM_TOTAL>>>(
        (const unsigned char*)p_xh, (const unsigned char*)p_wh, bias, out);
}